// round 2
// baseline (speedup 1.0000x reference)
#include <cuda_runtime.h>
#include <math.h>

#define BB 16
#define CH 128
#define NLEV 13
#define VFSZ (BB*128*CH)     // 262144
#define WSZ  (128*128*128)   // 2097152
#define TAB_TOTAL 1026985
#define SBUF (BB*4096*CH)    // 8388608

static const int h_m[NLEV]    = {4096,2048,1024,512,256,128,64,32,16,8,4,2,1};
static const int h_l[NLEV]    = {128,128,128,128,128,65,33,17,9,5,3,2,1};
static const int h_toff[NLEV] = {0,524288,786432,917504,983040,1015808,1024128,1026240,1026784,1026928,1026968,1026980,1026984};
static const int h_uoff[NLEV] = {0,4096,6144,7168,7680,7936,8064,8128,8160,8176,8184,8188,8190}; // prefix of m

// DFT tables: FC/FS forward (cos, -sin); IC/IS inverse (c_f*cos/m, -c_f*sin/m)
__device__ float g_FC[TAB_TOTAL];
__device__ float g_FS[TAB_TOTAL];
__device__ float g_IC[TAB_TOTAL];
__device__ float g_IS[TAB_TOTAL];

__device__ float g_Wt[6][WSZ];     // [w][f][i*128+o]
__device__ float g_D[SBUF];
__device__ float g_S[2][SBUF];
__device__ float g_UD[BB*CH*8191];
__device__ float g_US[BB*CH*8191];
__device__ float g_VF[4][VFSZ];    // Vd_r, Vd_i, Vs_r, Vs_i  (b,f,o): b*16384 + f*128 + o
__device__ float g_OF[4][VFSZ];    // OFud_r, OFud_i, OFus_r, OFus_i

// ---------------- table init ----------------
__global__ void k_init_tab(int m, int l, int toff) {
    int e = blockIdx.x * blockDim.x + threadIdx.x;
    if (e >= l * m) return;
    int f = e / m, t = e - f * m;
    int p = (int)(((long long)f * t) & (long long)(m - 1)); // f*t mod m (m pow2)
    float ang = 2.0f * (float)p / (float)m;
    float s, c;
    sincospif(ang, &s, &c);
    g_FC[toff + e] = c;
    g_FS[toff + e] = -s;
    float cf = (f == 0 || 2 * f == m) ? 1.0f : 2.0f;
    float inv = cf / (float)m;
    g_IC[toff + e] = c * inv;
    g_IS[toff + e] = -s * inv;
}

// ---------------- weight transpose: W[i][o][f] -> Wt[f][i*128+o] ----------------
__global__ void k_wt6(const float* __restrict__ p0, const float* __restrict__ p1,
                      const float* __restrict__ p2, const float* __restrict__ p3,
                      const float* __restrict__ p4, const float* __restrict__ p5) {
    int w = blockIdx.z;
    const float* W = (w == 0) ? p0 : (w == 1) ? p1 : (w == 2) ? p2 : (w == 3) ? p3 : (w == 4) ? p4 : p5;
    __shared__ float tile[32][33];
    int io0 = blockIdx.x * 32, f0 = blockIdx.y * 32;
    int tx = threadIdx.x, ty = threadIdx.y;
    #pragma unroll
    for (int r = ty; r < 32; r += 8)
        tile[r][tx] = W[(io0 + r) * 128 + f0 + tx];
    __syncthreads();
    #pragma unroll
    for (int r = ty; r < 32; r += 8)
        g_Wt[w][(f0 + r) * 16384 + io0 + tx] = tile[tx][r];
}

// ---------------- decompose: x(B,2m,128) -> d,s (B,m,128) ----------------
__global__ void k_dec(const float* __restrict__ xin, const float* __restrict__ ecs,
                      const float* __restrict__ ecd, float* __restrict__ dout,
                      float* __restrict__ sout, int m) {
    __shared__ float se[32], sd2[32];
    if (threadIdx.x < 32) { se[threadIdx.x] = ecs[threadIdx.x]; sd2[threadIdx.x] = ecd[threadIdx.x]; }
    __syncthreads();
    int idx = blockIdx.x * blockDim.x + threadIdx.x;
    if (idx >= 16 * m * 32) return;
    int c = idx & 31;
    int bm = idx >> 5;
    int t = bm & (m - 1);
    int b = bm / m;
    long base = ((long)b * 2 * m + 2 * t) * 128 + c * 4;
    float4 xe = *(const float4*)(xin + base);
    float4 xo = *(const float4*)(xin + base + 128);
    float xa[8] = {xe.x, xe.y, xe.z, xe.w, xo.x, xo.y, xo.z, xo.w};
    float dd[4] = {0, 0, 0, 0}, ss[4] = {0, 0, 0, 0};
    #pragma unroll
    for (int j = 0; j < 8; j++) {
        float xv = xa[j];
        #pragma unroll
        for (int k = 0; k < 4; k++) {
            dd[k] = fmaf(xv, sd2[j * 4 + k], dd[k]);
            ss[k] = fmaf(xv, se[j * 4 + k], ss[k]);
        }
    }
    long ob = ((long)b * m + t) * 128 + c * 4;
    *(float4*)(dout + ob) = make_float4(dd[0], dd[1], dd[2], dd[3]);
    *(float4*)(sout + ob) = make_float4(ss[0], ss[1], ss[2], ss[3]);
}

// ---------------- forward partial DFT (both d and s, cos & sin) ----------------
// Vf[b,f,o] = sum_t FC[f,t] * v[b,t,o]  (and FS for imag)
__global__ __launch_bounds__(256) void k_fwd(const float* __restrict__ dsig,
                                             const float* __restrict__ ssig,
                                             float* __restrict__ vf,
                                             int m, int l, int toff) {
    int sig = blockIdx.z >> 4;
    int b = blockIdx.z & 15;
    const float* src = sig ? ssig : dsig;
    float* outR = vf + (sig * 2 + 0) * VFSZ + b * 16384;
    float* outI = vf + (sig * 2 + 1) * VFSZ + b * 16384;
    int f0 = blockIdx.x * 64, o0 = blockIdx.y * 64;
    __shared__ float Ac[16][64], As[16][64], Bs[16][64];
    int tx = threadIdx.x, ty = threadIdx.y, tid = ty * 16 + tx;
    float accC[4][4] = {}, accS[4][4] = {};
    for (int kk = 0; kk < m; kk += 16) {
        #pragma unroll
        for (int p = 0; p < 4; p++) {
            int e = tid + p * 256;
            int tt = e & 15, ff = e >> 4;
            float ac = 0.f, as = 0.f;
            int f = f0 + ff, t = kk + tt;
            if (f < l && t < m) { int a = toff + f * m + t; ac = g_FC[a]; as = g_FS[a]; }
            Ac[tt][ff] = ac; As[tt][ff] = as;
        }
        #pragma unroll
        for (int p = 0; p < 4; p++) {
            int e = tid + p * 256;
            int oo = e & 63, tt = e >> 6;
            float v = 0.f;
            int t = kk + tt;
            if (t < m) v = src[((long)b * m + t) * 128 + o0 + oo];
            Bs[tt][oo] = v;
        }
        __syncthreads();
        #pragma unroll
        for (int k = 0; k < 16; k++) {
            float a_c[4], a_s[4], bv[4];
            #pragma unroll
            for (int i = 0; i < 4; i++) { a_c[i] = Ac[k][ty * 4 + i]; a_s[i] = As[k][ty * 4 + i]; }
            #pragma unroll
            for (int j = 0; j < 4; j++) bv[j] = Bs[k][tx * 4 + j];
            #pragma unroll
            for (int i = 0; i < 4; i++)
                #pragma unroll
                for (int j = 0; j < 4; j++) {
                    accC[i][j] = fmaf(a_c[i], bv[j], accC[i][j]);
                    accS[i][j] = fmaf(a_s[i], bv[j], accS[i][j]);
                }
        }
        __syncthreads();
    }
    #pragma unroll
    for (int i = 0; i < 4; i++) {
        int f = f0 + ty * 4 + i;
        if (f < l) {
            #pragma unroll
            for (int j = 0; j < 4; j++) {
                int o = o0 + tx * 4 + j;
                outR[f * 128 + o] = accC[i][j];
                outI[f * 128 + o] = accS[i][j];
            }
        }
    }
}

// ---------------- mode mix: OF[b,f,o] = sum_i V[b,f,i] * W[f][i][o] (complex) ----------------
__global__ __launch_bounds__(128) void k_mix(const float* __restrict__ W1r, const float* __restrict__ W1i,
                                             const float* __restrict__ V1r, const float* __restrict__ V1i,
                                             const float* __restrict__ W2r, const float* __restrict__ W2i,
                                             const float* __restrict__ V2r, const float* __restrict__ V2i,
                                             float* __restrict__ OFr, float* __restrict__ OFi, int two) {
    int f = blockIdx.x;
    int o = threadIdx.x;
    __shared__ float2 sV[16 * 128]; // [b][i]
    float ar[16] = {}, ai[16] = {};
    #pragma unroll
    for (int j = 0; j < 16; j++)
        sV[j * 128 + o] = make_float2(V1r[j * 16384 + f * 128 + o], V1i[j * 16384 + f * 128 + o]);
    __syncthreads();
    for (int i = 0; i < 128; i++) {
        float wr = W1r[f * 16384 + i * 128 + o];
        float wi = W1i[f * 16384 + i * 128 + o];
        #pragma unroll
        for (int bb = 0; bb < 16; bb++) {
            float2 v = sV[bb * 128 + i];
            ar[bb] = fmaf(v.x, wr, fmaf(-v.y, wi, ar[bb]));
            ai[bb] = fmaf(v.x, wi, fmaf(v.y, wr, ai[bb]));
        }
    }
    if (two) {
        __syncthreads();
        #pragma unroll
        for (int j = 0; j < 16; j++)
            sV[j * 128 + o] = make_float2(V2r[j * 16384 + f * 128 + o], V2i[j * 16384 + f * 128 + o]);
        __syncthreads();
        for (int i = 0; i < 128; i++) {
            float wr = W2r[f * 16384 + i * 128 + o];
            float wi = W2i[f * 16384 + i * 128 + o];
            #pragma unroll
            for (int bb = 0; bb < 16; bb++) {
                float2 v = sV[bb * 128 + i];
                ar[bb] = fmaf(v.x, wr, fmaf(-v.y, wi, ar[bb]));
                ai[bb] = fmaf(v.x, wi, fmaf(v.y, wr, ai[bb]));
            }
        }
    }
    #pragma unroll
    for (int bb = 0; bb < 16; bb++) {
        OFr[bb * 16384 + f * 128 + o] = ar[bb];
        OFi[bb * 16384 + f * 128 + o] = ai[bb];
    }
}

// ---------------- inverse partial DFT: y[b,t,o] = sum_f IC[f,t]*OFr + IS[f,t]*OFi ----------------
__global__ __launch_bounds__(256) void k_inv(float* __restrict__ outUD, float* __restrict__ outUS,
                                             const float* __restrict__ of,
                                             int m, int l, int toff) {
    int sig = blockIdx.z >> 4;
    int b = blockIdx.z & 15;
    float* out = sig ? outUS : outUD;
    const float* BRp = of + (sig * 2 + 0) * VFSZ + b * 16384;
    const float* BIp = of + (sig * 2 + 1) * VFSZ + b * 16384;
    int t0 = blockIdx.x * 64, o0 = blockIdx.y * 64;
    __shared__ float Ac[16][64], As[16][64], Br[16][64], Bi[16][64];
    int tx = threadIdx.x, ty = threadIdx.y, tid = ty * 16 + tx;
    float acc[4][4] = {};
    for (int kk = 0; kk < l; kk += 16) {
        #pragma unroll
        for (int p = 0; p < 4; p++) {
            int e = tid + p * 256;
            int tt = e & 63, kr = e >> 6;
            float ac = 0.f, as = 0.f;
            int f = kk + kr, t = t0 + tt;
            if (f < l && t < m) { int a = toff + f * m + t; ac = g_IC[a]; as = g_IS[a]; }
            Ac[kr][tt] = ac; As[kr][tt] = as;
        }
        #pragma unroll
        for (int p = 0; p < 4; p++) {
            int e = tid + p * 256;
            int oo = e & 63, kr = e >> 6;
            float br = 0.f, bi = 0.f;
            int f = kk + kr;
            if (f < l) { br = BRp[f * 128 + o0 + oo]; bi = BIp[f * 128 + o0 + oo]; }
            Br[kr][oo] = br; Bi[kr][oo] = bi;
        }
        __syncthreads();
        #pragma unroll
        for (int k = 0; k < 16; k++) {
            float a_c[4], a_s[4], br[4], bi[4];
            #pragma unroll
            for (int i = 0; i < 4; i++) { a_c[i] = Ac[k][ty * 4 + i]; a_s[i] = As[k][ty * 4 + i]; }
            #pragma unroll
            for (int j = 0; j < 4; j++) { br[j] = Br[k][tx * 4 + j]; bi[j] = Bi[k][tx * 4 + j]; }
            #pragma unroll
            for (int i = 0; i < 4; i++)
                #pragma unroll
                for (int j = 0; j < 4; j++)
                    acc[i][j] = fmaf(a_c[i], br[j], fmaf(a_s[i], bi[j], acc[i][j]));
        }
        __syncthreads();
    }
    #pragma unroll
    for (int i = 0; i < 4; i++) {
        int t = t0 + ty * 4 + i;
        if (t < m) {
            #pragma unroll
            for (int j = 0; j < 4; j++)
                out[((long)b * m + t) * 128 + o0 + tx * 4 + j] = acc[i][j];
        }
    }
}

// ---------------- coarsest T0: y = x @ T0_w^T + b ----------------
__global__ void k_t0(const float* __restrict__ xin, const float* __restrict__ w,
                     const float* __restrict__ bias, float* __restrict__ xout) {
    int idx = blockIdx.x * blockDim.x + threadIdx.x;
    if (idx >= 512) return;
    float4 xv = *(const float4*)(xin + idx * 4);
    float xa[4] = {xv.x, xv.y, xv.z, xv.w};
    float y[4];
    #pragma unroll
    for (int k = 0; k < 4; k++) {
        float acc = bias[k];
        #pragma unroll
        for (int j = 0; j < 4; j++) acc = fmaf(xa[j], w[k * 4 + j], acc);
        y[k] = acc;
    }
    *(float4*)(xout + idx * 4) = make_float4(y[0], y[1], y[2], y[3]);
}

// ---------------- reconstruct: (x+Us, Ud) -> interleaved 2m ----------------
__global__ void k_rec(const float* __restrict__ xin, const float* __restrict__ ud,
                      const float* __restrict__ us, const float* __restrict__ rce,
                      const float* __restrict__ rco, float* __restrict__ xout, int m) {
    __shared__ float se[32], so[32];
    if (threadIdx.x < 32) { se[threadIdx.x] = rce[threadIdx.x]; so[threadIdx.x] = rco[threadIdx.x]; }
    __syncthreads();
    int idx = blockIdx.x * blockDim.x + threadIdx.x;
    if (idx >= 16 * m * 32) return;
    int c = idx & 31;
    int bm = idx >> 5;
    int t = bm & (m - 1);
    int b = bm / m;
    long ib = ((long)b * m + t) * 128 + c * 4;
    float4 xv = *(const float4*)(xin + ib);
    float4 uv = *(const float4*)(us + ib);
    float4 dv = *(const float4*)(ud + ib);
    float xx[8] = {xv.x + uv.x, xv.y + uv.y, xv.z + uv.z, xv.w + uv.w, dv.x, dv.y, dv.z, dv.w};
    float xe[4] = {0, 0, 0, 0}, xo[4] = {0, 0, 0, 0};
    #pragma unroll
    for (int j = 0; j < 8; j++) {
        float xj = xx[j];
        #pragma unroll
        for (int k = 0; k < 4; k++) {
            xe[k] = fmaf(xj, se[j * 4 + k], xe[k]);
            xo[k] = fmaf(xj, so[j * 4 + k], xo[k]);
        }
    }
    long ob = ((long)b * 2 * m + 2 * t) * 128 + c * 4;
    *(float4*)(xout + ob) = make_float4(xe[0], xe[1], xe[2], xe[3]);
    *(float4*)(xout + ob + 128) = make_float4(xo[0], xo[1], xo[2], xo[3]);
}

extern "C" void kernel_launch(void* const* d_in, const int* in_sizes, int n_in,
                              void* d_out, int out_size) {
    const float* x = (const float*)d_in[0];
    const float* W6[6];
    for (int i = 0; i < 6; i++) W6[i] = (const float*)d_in[1 + i];
    // remaining inputs identified by size (robust to T0 vs ec/rc ordering)
    const float* small32[4] = {0, 0, 0, 0};
    const float* T0w = 0; const float* T0b = 0;
    int n32 = 0;
    for (int i = 7; i < n_in; i++) {
        int s = in_sizes[i];
        if (s == 32 && n32 < 4) small32[n32++] = (const float*)d_in[i];
        else if (s == 16) T0w = (const float*)d_in[i];
        else if (s == 4) T0b = (const float*)d_in[i];
    }
    const float* ec_s = small32[0];
    const float* ec_d = small32[1];
    const float* rc_e = small32[2];
    const float* rc_o = small32[3];

    float *pD, *pS, *pUD, *pUS, *pVF, *pOF, *pWt;
    cudaGetSymbolAddress((void**)&pD, g_D);
    cudaGetSymbolAddress((void**)&pS, g_S);
    cudaGetSymbolAddress((void**)&pUD, g_UD);
    cudaGetSymbolAddress((void**)&pUS, g_US);
    cudaGetSymbolAddress((void**)&pVF, g_VF);
    cudaGetSymbolAddress((void**)&pOF, g_OF);
    cudaGetSymbolAddress((void**)&pWt, g_Wt);
    float* pS0 = pS;
    float* pS1 = pS + SBUF;

    // 1. DFT tables
    for (int i = 0; i < NLEV; i++) {
        int tot = h_l[i] * h_m[i];
        k_init_tab<<<(tot + 255) / 256, 256>>>(h_m[i], h_l[i], h_toff[i]);
    }
    // 2. weight transpose
    {
        dim3 g(512, 4, 6);
        k_wt6<<<g, dim3(32, 8)>>>(W6[0], W6[1], W6[2], W6[3], W6[4], W6[5]);
    }

    // 3. decompose + skft per level
    const float* xin = x;
    for (int i = 0; i < NLEV; i++) {
        int m = h_m[i], l = h_l[i], toff = h_toff[i];
        float* sout = (i & 1) ? pS1 : pS0;
        int tot = BB * m * 32;
        k_dec<<<(tot + 255) / 256, 256>>>(xin, ec_s, ec_d, pD, sout, m);
        dim3 gf((l + 63) / 64, 2, 32);
        k_fwd<<<gf, dim3(16, 16)>>>(pD, sout, pVF, m, l, toff);
        // Ud spectrum: A(d) + B(s)
        k_mix<<<l, 128>>>(pWt + 0 * WSZ, pWt + 1 * WSZ, pVF + 0 * VFSZ, pVF + 1 * VFSZ,
                          pWt + 2 * WSZ, pWt + 3 * WSZ, pVF + 2 * VFSZ, pVF + 3 * VFSZ,
                          pOF + 0 * VFSZ, pOF + 1 * VFSZ, 1);
        // Us spectrum: C(d)
        k_mix<<<l, 128>>>(pWt + 4 * WSZ, pWt + 5 * WSZ, pVF + 0 * VFSZ, pVF + 1 * VFSZ,
                          0, 0, 0, 0,
                          pOF + 2 * VFSZ, pOF + 3 * VFSZ, 0);
        dim3 gi((m + 63) / 64, 2, 32);
        k_inv<<<gi, dim3(16, 16)>>>(pUD + (long)h_uoff[i] * (BB * CH),
                                    pUS + (long)h_uoff[i] * (BB * CH),
                                    pOF, m, l, toff);
        xin = sout;
    }

    // 4. T0 at coarsest scale (level 12 output lives in pS0)
    k_t0<<<2, 256>>>(pS0, T0w, T0b, pS1);

    // 5. reconstruct
    float* rin = pS1;
    for (int i = NLEV - 1; i >= 0; i--) {
        int m = h_m[i];
        float* rout = (i == 0) ? (float*)d_out : ((rin == pS1) ? pS0 : pS1);
        int tot = BB * m * 32;
        k_rec<<<(tot + 255) / 256, 256>>>(rin,
                                          pUD + (long)h_uoff[i] * (BB * CH),
                                          pUS + (long)h_uoff[i] * (BB * CH),
                                          rc_e, rc_o, rout, m);
        rin = rout;
    }
}

// round 5
// speedup vs baseline: 1.2687x; 1.2687x over previous
#include <cuda_runtime.h>
#include <math.h>

#define BB 16
#define CH 128
#define NLEV 13
#define VFSZ (BB*128*CH)     // 262144
#define WSZ  (128*128*128)   // 2097152
#define TAB_TOTAL 1026985
#define SBUF (BB*4096*CH)    // 8388608

typedef unsigned long long u64;

static const int h_m[NLEV]    = {4096,2048,1024,512,256,128,64,32,16,8,4,2,1};
static const int h_l[NLEV]    = {128,128,128,128,128,65,33,17,9,5,3,2,1};
static const int h_toff[NLEV] = {0,524288,786432,917504,983040,1015808,1024128,1026240,1026784,1026928,1026968,1026980,1026984};
static const int h_uoff[NLEV] = {0,4096,6144,7168,7680,7936,8064,8128,8160,8176,8184,8188,8190};

// DFT tables: FC/FS forward (cos, -sin); IC/IS inverse (c_f*cos/m, -c_f*sin/m)
__device__ float g_FC[TAB_TOTAL];
__device__ float g_FS[TAB_TOTAL];
__device__ float g_IC[TAB_TOTAL];
__device__ float g_IS[TAB_TOTAL];

__device__ float g_Wt[6][WSZ];     // [w][f][i*128+o]
__device__ float g_D[SBUF];
__device__ float g_S[2][SBUF];
__device__ float g_UD[BB*CH*8191];
__device__ float g_US[BB*CH*8191];
__device__ float g_VF[4][VFSZ];    // Vd_r, Vd_i, Vs_r, Vs_i  (b,f,o)
__device__ float g_OF[4][VFSZ];

// ---- packed f32x2 helpers (FFMA2) ----
__device__ __forceinline__ u64 pk2(float lo, float hi) {
    u64 r; asm("mov.b64 %0, {%1, %2};" : "=l"(r) : "f"(lo), "f"(hi)); return r;
}
__device__ __forceinline__ float2 up2(u64 v) {
    float2 r; asm("mov.b64 {%0, %1}, %2;" : "=f"(r.x), "=f"(r.y) : "l"(v)); return r;
}
__device__ __forceinline__ u64 fma2(u64 a, u64 b, u64 c) {
    u64 d; asm("fma.rn.f32x2 %0, %1, %2, %3;" : "=l"(d) : "l"(a), "l"(b), "l"(c)); return d;
}
__device__ __forceinline__ u64 lds2(const float2& p) {
    return *reinterpret_cast<const u64*>(&p);
}

// ---------------- table init ----------------
__global__ void k_init_tab(int m, int l, int toff) {
    int e = blockIdx.x * blockDim.x + threadIdx.x;
    if (e >= l * m) return;
    int f = e / m, t = e - f * m;
    int p = (int)(((long long)f * t) & (long long)(m - 1));
    float ang = 2.0f * (float)p / (float)m;
    float s, c;
    sincospif(ang, &s, &c);
    g_FC[toff + e] = c;
    g_FS[toff + e] = -s;
    float cf = (f == 0 || 2 * f == m) ? 1.0f : 2.0f;
    float inv = cf / (float)m;
    g_IC[toff + e] = c * inv;
    g_IS[toff + e] = -s * inv;
}

// ---------------- weight transpose: W[i][o][f] -> Wt[f][i*128+o] ----------------
__global__ void k_wt6(const float* __restrict__ p0, const float* __restrict__ p1,
                      const float* __restrict__ p2, const float* __restrict__ p3,
                      const float* __restrict__ p4, const float* __restrict__ p5) {
    int w = blockIdx.z;
    const float* W = (w == 0) ? p0 : (w == 1) ? p1 : (w == 2) ? p2 : (w == 3) ? p3 : (w == 4) ? p4 : p5;
    __shared__ float tile[32][33];
    int io0 = blockIdx.x * 32, f0 = blockIdx.y * 32;
    int tx = threadIdx.x, ty = threadIdx.y;
    #pragma unroll
    for (int r = ty; r < 32; r += 8)
        tile[r][tx] = W[(io0 + r) * 128 + f0 + tx];
    __syncthreads();
    #pragma unroll
    for (int r = ty; r < 32; r += 8)
        g_Wt[w][(f0 + r) * 16384 + io0 + tx] = tile[tx][r];
}

// ---------------- decompose ----------------
__global__ void k_dec(const float* __restrict__ xin, const float* __restrict__ ecs,
                      const float* __restrict__ ecd, float* __restrict__ dout,
                      float* __restrict__ sout, int m) {
    __shared__ float se[32], sd2[32];
    if (threadIdx.x < 32) { se[threadIdx.x] = ecs[threadIdx.x]; sd2[threadIdx.x] = ecd[threadIdx.x]; }
    __syncthreads();
    int idx = blockIdx.x * blockDim.x + threadIdx.x;
    if (idx >= 16 * m * 32) return;
    int c = idx & 31;
    int bm = idx >> 5;
    int t = bm & (m - 1);
    int b = bm / m;
    long base = ((long)b * 2 * m + 2 * t) * 128 + c * 4;
    float4 xe = *(const float4*)(xin + base);
    float4 xo = *(const float4*)(xin + base + 128);
    float xa[8] = {xe.x, xe.y, xe.z, xe.w, xo.x, xo.y, xo.z, xo.w};
    float dd[4] = {0, 0, 0, 0}, ss[4] = {0, 0, 0, 0};
    #pragma unroll
    for (int j = 0; j < 8; j++) {
        float xv = xa[j];
        #pragma unroll
        for (int k = 0; k < 4; k++) {
            dd[k] = fmaf(xv, sd2[j * 4 + k], dd[k]);
            ss[k] = fmaf(xv, se[j * 4 + k], ss[k]);
        }
    }
    long ob = ((long)b * m + t) * 128 + c * 4;
    *(float4*)(dout + ob) = make_float4(dd[0], dd[1], dd[2], dd[3]);
    *(float4*)(sout + ob) = make_float4(ss[0], ss[1], ss[2], ss[3]);
}

// ---------------- forward partial DFT (FFMA2: (cos,sin) pairs) ----------------
__global__ __launch_bounds__(256) void k_fwd(const float* __restrict__ dsig,
                                             const float* __restrict__ ssig,
                                             float* __restrict__ vf,
                                             int m, int l, int toff) {
    int sig = blockIdx.z >> 4;
    int b = blockIdx.z & 15;
    const float* src = sig ? ssig : dsig;
    float* outR = vf + (sig * 2 + 0) * VFSZ + b * 16384;
    float* outI = vf + (sig * 2 + 1) * VFSZ + b * 16384;
    int f0 = blockIdx.x * 64, o0 = blockIdx.y * 64;
    __shared__ float2 Acs[16][64];   // (cos, -sin) interleaved
    __shared__ float2 Bd[16][64];    // (v, v) duplicated
    int tx = threadIdx.x, ty = threadIdx.y, tid = ty * 16 + tx;
    u64 acc2[4][4] = {};
    for (int kk = 0; kk < m; kk += 16) {
        #pragma unroll
        for (int p = 0; p < 4; p++) {
            int e = tid + p * 256;
            int tt = e & 15, ff = e >> 4;
            float ac = 0.f, as = 0.f;
            int f = f0 + ff, t = kk + tt;
            if (f < l && t < m) { int a = toff + f * m + t; ac = g_FC[a]; as = g_FS[a]; }
            Acs[tt][ff] = make_float2(ac, as);
        }
        #pragma unroll
        for (int p = 0; p < 4; p++) {
            int e = tid + p * 256;
            int oo = e & 63, tt = e >> 6;
            float v = 0.f;
            int t = kk + tt;
            if (t < m) v = src[((long)b * m + t) * 128 + o0 + oo];
            Bd[tt][oo] = make_float2(v, v);
        }
        __syncthreads();
        #pragma unroll
        for (int k = 0; k < 16; k++) {
            u64 a2[4], b2[4];
            #pragma unroll
            for (int i = 0; i < 4; i++) a2[i] = lds2(Acs[k][ty * 4 + i]);
            #pragma unroll
            for (int j = 0; j < 4; j++) b2[j] = lds2(Bd[k][tx * 4 + j]);
            #pragma unroll
            for (int i = 0; i < 4; i++)
                #pragma unroll
                for (int j = 0; j < 4; j++)
                    acc2[i][j] = fma2(a2[i], b2[j], acc2[i][j]);
        }
        __syncthreads();
    }
    #pragma unroll
    for (int i = 0; i < 4; i++) {
        int f = f0 + ty * 4 + i;
        if (f < l) {
            #pragma unroll
            for (int j = 0; j < 4; j++) {
                int o = o0 + tx * 4 + j;
                float2 cs = up2(acc2[i][j]);
                outR[f * 128 + o] = cs.x;
                outI[f * 128 + o] = cs.y;
            }
        }
    }
}

// ---------------- mode mix (FFMA2: (re,im) pairs) ----------------
__global__ __launch_bounds__(128) void k_mix(const float* __restrict__ W1r, const float* __restrict__ W1i,
                                             const float* __restrict__ V1r, const float* __restrict__ V1i,
                                             const float* __restrict__ W2r, const float* __restrict__ W2i,
                                             const float* __restrict__ V2r, const float* __restrict__ V2i,
                                             float* __restrict__ OFr, float* __restrict__ OFi, int two) {
    int f = blockIdx.x;
    int o = threadIdx.x;
    __shared__ float2 sVx[16][128];   // (vx, vx)
    __shared__ float2 sVny[16][128];  // (-vy, vy)
    u64 acc2[16] = {};
    #pragma unroll
    for (int j = 0; j < 16; j++) {
        float vx = V1r[j * 16384 + f * 128 + o];
        float vy = V1i[j * 16384 + f * 128 + o];
        sVx[j][o] = make_float2(vx, vx);
        sVny[j][o] = make_float2(-vy, vy);
    }
    __syncthreads();
    for (int i = 0; i < 128; i++) {
        float wr = W1r[f * 16384 + i * 128 + o];
        float wi = W1i[f * 16384 + i * 128 + o];
        u64 wri = pk2(wr, wi);
        u64 wir = pk2(wi, wr);
        #pragma unroll
        for (int bb = 0; bb < 16; bb++) {
            acc2[bb] = fma2(lds2(sVx[bb][i]), wri, acc2[bb]);
            acc2[bb] = fma2(lds2(sVny[bb][i]), wir, acc2[bb]);
        }
    }
    if (two) {
        __syncthreads();
        #pragma unroll
        for (int j = 0; j < 16; j++) {
            float vx = V2r[j * 16384 + f * 128 + o];
            float vy = V2i[j * 16384 + f * 128 + o];
            sVx[j][o] = make_float2(vx, vx);
            sVny[j][o] = make_float2(-vy, vy);
        }
        __syncthreads();
        for (int i = 0; i < 128; i++) {
            float wr = W2r[f * 16384 + i * 128 + o];
            float wi = W2i[f * 16384 + i * 128 + o];
            u64 wri = pk2(wr, wi);
            u64 wir = pk2(wi, wr);
            #pragma unroll
            for (int bb = 0; bb < 16; bb++) {
                acc2[bb] = fma2(lds2(sVx[bb][i]), wri, acc2[bb]);
                acc2[bb] = fma2(lds2(sVny[bb][i]), wir, acc2[bb]);
            }
        }
    }
    #pragma unroll
    for (int bb = 0; bb < 16; bb++) {
        float2 ri = up2(acc2[bb]);
        OFr[bb * 16384 + f * 128 + o] = ri.x;
        OFi[bb * 16384 + f * 128 + o] = ri.y;
    }
}

// ---------------- inverse partial DFT (FFMA2: o pairs, dup A) ----------------
__global__ __launch_bounds__(256) void k_inv(float* __restrict__ outUD, float* __restrict__ outUS,
                                             const float* __restrict__ of,
                                             int m, int l, int toff) {
    int sig = blockIdx.z >> 4;
    int b = blockIdx.z & 15;
    float* out = sig ? outUS : outUD;
    const float* BRp = of + (sig * 2 + 0) * VFSZ + b * 16384;
    const float* BIp = of + (sig * 2 + 1) * VFSZ + b * 16384;
    int t0 = blockIdx.x * 64, o0 = blockIdx.y * 64;
    __shared__ float2 Acd[16][64];   // (ic, ic) duplicated
    __shared__ float2 Asd[16][64];   // (is, is) duplicated
    __shared__ float Br[16][64], Bi[16][64];
    int tx = threadIdx.x, ty = threadIdx.y, tid = ty * 16 + tx;
    u64 acc2[4][2] = {};
    for (int kk = 0; kk < l; kk += 16) {
        #pragma unroll
        for (int p = 0; p < 4; p++) {
            int e = tid + p * 256;
            int tt = e & 63, kr = e >> 6;
            float ac = 0.f, as = 0.f;
            int f = kk + kr, t = t0 + tt;
            if (f < l && t < m) { int a = toff + f * m + t; ac = g_IC[a]; as = g_IS[a]; }
            Acd[kr][tt] = make_float2(ac, ac);
            Asd[kr][tt] = make_float2(as, as);
        }
        #pragma unroll
        for (int p = 0; p < 4; p++) {
            int e = tid + p * 256;
            int oo = e & 63, kr = e >> 6;
            float br = 0.f, bi = 0.f;
            int f = kk + kr;
            if (f < l) { br = BRp[f * 128 + o0 + oo]; bi = BIp[f * 128 + o0 + oo]; }
            Br[kr][oo] = br; Bi[kr][oo] = bi;
        }
        __syncthreads();
        #pragma unroll
        for (int k = 0; k < 16; k++) {
            u64 ac2[4], as2[4], br2[2], bi2[2];
            #pragma unroll
            for (int i = 0; i < 4; i++) { ac2[i] = lds2(Acd[k][ty * 4 + i]); as2[i] = lds2(Asd[k][ty * 4 + i]); }
            #pragma unroll
            for (int j = 0; j < 2; j++) {
                br2[j] = *reinterpret_cast<const u64*>(&Br[k][tx * 4 + 2 * j]);
                bi2[j] = *reinterpret_cast<const u64*>(&Bi[k][tx * 4 + 2 * j]);
            }
            #pragma unroll
            for (int i = 0; i < 4; i++)
                #pragma unroll
                for (int j = 0; j < 2; j++) {
                    acc2[i][j] = fma2(ac2[i], br2[j], acc2[i][j]);
                    acc2[i][j] = fma2(as2[i], bi2[j], acc2[i][j]);
                }
        }
        __syncthreads();
    }
    #pragma unroll
    for (int i = 0; i < 4; i++) {
        int t = t0 + ty * 4 + i;
        if (t < m) {
            float2 p0 = up2(acc2[i][0]);
            float2 p1 = up2(acc2[i][1]);
            *(float4*)(out + ((long)b * m + t) * 128 + o0 + tx * 4) = make_float4(p0.x, p0.y, p1.x, p1.y);
        }
    }
}

// ---------------- coarsest T0 ----------------
__global__ void k_t0(const float* __restrict__ xin, const float* __restrict__ w,
                     const float* __restrict__ bias, float* __restrict__ xout) {
    int idx = blockIdx.x * blockDim.x + threadIdx.x;
    if (idx >= 512) return;
    float4 xv = *(const float4*)(xin + idx * 4);
    float xa[4] = {xv.x, xv.y, xv.z, xv.w};
    float y[4];
    #pragma unroll
    for (int k = 0; k < 4; k++) {
        float acc = bias[k];
        #pragma unroll
        for (int j = 0; j < 4; j++) acc = fmaf(xa[j], w[k * 4 + j], acc);
        y[k] = acc;
    }
    *(float4*)(xout + idx * 4) = make_float4(y[0], y[1], y[2], y[3]);
}

// ---------------- reconstruct ----------------
__global__ void k_rec(const float* __restrict__ xin, const float* __restrict__ ud,
                      const float* __restrict__ us, const float* __restrict__ rce,
                      const float* __restrict__ rco, float* __restrict__ xout, int m) {
    __shared__ float se[32], so[32];
    if (threadIdx.x < 32) { se[threadIdx.x] = rce[threadIdx.x]; so[threadIdx.x] = rco[threadIdx.x]; }
    __syncthreads();
    int idx = blockIdx.x * blockDim.x + threadIdx.x;
    if (idx >= 16 * m * 32) return;
    int c = idx & 31;
    int bm = idx >> 5;
    int t = bm & (m - 1);
    int b = bm / m;
    long ib = ((long)b * m + t) * 128 + c * 4;
    float4 xv = *(const float4*)(xin + ib);
    float4 uv = *(const float4*)(us + ib);
    float4 dv = *(const float4*)(ud + ib);
    float xx[8] = {xv.x + uv.x, xv.y + uv.y, xv.z + uv.z, xv.w + uv.w, dv.x, dv.y, dv.z, dv.w};
    float xe[4] = {0, 0, 0, 0}, xo[4] = {0, 0, 0, 0};
    #pragma unroll
    for (int j = 0; j < 8; j++) {
        float xj = xx[j];
        #pragma unroll
        for (int k = 0; k < 4; k++) {
            xe[k] = fmaf(xj, se[j * 4 + k], xe[k]);
            xo[k] = fmaf(xj, so[j * 4 + k], xo[k]);
        }
    }
    long ob = ((long)b * 2 * m + 2 * t) * 128 + c * 4;
    *(float4*)(xout + ob) = make_float4(xe[0], xe[1], xe[2], xe[3]);
    *(float4*)(xout + ob + 128) = make_float4(xo[0], xo[1], xo[2], xo[3]);
}

extern "C" void kernel_launch(void* const* d_in, const int* in_sizes, int n_in,
                              void* d_out, int out_size) {
    const float* x = (const float*)d_in[0];
    const float* W6[6];
    for (int i = 0; i < 6; i++) W6[i] = (const float*)d_in[1 + i];
    const float* small32[4] = {0, 0, 0, 0};
    const float* T0w = 0; const float* T0b = 0;
    int n32 = 0;
    for (int i = 7; i < n_in; i++) {
        int s = in_sizes[i];
        if (s == 32 && n32 < 4) small32[n32++] = (const float*)d_in[i];
        else if (s == 16) T0w = (const float*)d_in[i];
        else if (s == 4) T0b = (const float*)d_in[i];
    }
    const float* ec_s = small32[0];
    const float* ec_d = small32[1];
    const float* rc_e = small32[2];
    const float* rc_o = small32[3];

    float *pD, *pS, *pUD, *pUS, *pVF, *pOF, *pWt;
    cudaGetSymbolAddress((void**)&pD, g_D);
    cudaGetSymbolAddress((void**)&pS, g_S);
    cudaGetSymbolAddress((void**)&pUD, g_UD);
    cudaGetSymbolAddress((void**)&pUS, g_US);
    cudaGetSymbolAddress((void**)&pVF, g_VF);
    cudaGetSymbolAddress((void**)&pOF, g_OF);
    cudaGetSymbolAddress((void**)&pWt, g_Wt);
    float* pS0 = pS;
    float* pS1 = pS + SBUF;

    for (int i = 0; i < NLEV; i++) {
        int tot = h_l[i] * h_m[i];
        k_init_tab<<<(tot + 255) / 256, 256>>>(h_m[i], h_l[i], h_toff[i]);
    }
    {
        dim3 g(512, 4, 6);
        k_wt6<<<g, dim3(32, 8)>>>(W6[0], W6[1], W6[2], W6[3], W6[4], W6[5]);
    }

    const float* xin = x;
    for (int i = 0; i < NLEV; i++) {
        int m = h_m[i], l = h_l[i], toff = h_toff[i];
        float* sout = (i & 1) ? pS1 : pS0;
        int tot = BB * m * 32;
        k_dec<<<(tot + 255) / 256, 256>>>(xin, ec_s, ec_d, pD, sout, m);
        dim3 gf((l + 63) / 64, 2, 32);
        k_fwd<<<gf, dim3(16, 16)>>>(pD, sout, pVF, m, l, toff);
        k_mix<<<l, 128>>>(pWt + 0 * WSZ, pWt + 1 * WSZ, pVF + 0 * VFSZ, pVF + 1 * VFSZ,
                          pWt + 2 * WSZ, pWt + 3 * WSZ, pVF + 2 * VFSZ, pVF + 3 * VFSZ,
                          pOF + 0 * VFSZ, pOF + 1 * VFSZ, 1);
        k_mix<<<l, 128>>>(pWt + 4 * WSZ, pWt + 5 * WSZ, pVF + 0 * VFSZ, pVF + 1 * VFSZ,
                          0, 0, 0, 0,
                          pOF + 2 * VFSZ, pOF + 3 * VFSZ, 0);
        dim3 gi((m + 63) / 64, 2, 32);
        k_inv<<<gi, dim3(16, 16)>>>(pUD + (long)h_uoff[i] * (BB * CH),
                                    pUS + (long)h_uoff[i] * (BB * CH),
                                    pOF, m, l, toff);
        xin = sout;
    }

    k_t0<<<2, 256>>>(pS0, T0w, T0b, pS1);

    float* rin = pS1;
    for (int i = NLEV - 1; i >= 0; i--) {
        int m = h_m[i];
        float* rout = (i == 0) ? (float*)d_out : ((rin == pS1) ? pS0 : pS1);
        int tot = BB * m * 32;
        k_rec<<<(tot + 255) / 256, 256>>>(rin,
                                          pUD + (long)h_uoff[i] * (BB * CH),
                                          pUS + (long)h_uoff[i] * (BB * CH),
                                          rc_e, rc_o, rout, m);
        rin = rout;
    }
}

// round 9
// speedup vs baseline: 1.4673x; 1.1566x over previous
#include <cuda_runtime.h>
#include <math.h>

#define BB 16
#define CH 128
#define NLEV 13
#define VFSZ (BB*128*CH)     // 262144
#define WSZ  (128*128*128)   // 2097152
#define TAB_TOTAL 1026985
#define SBUF (BB*4096*CH)    // 8388608
#define MAXSP 8
#define KCHUNK 512

typedef unsigned long long u64;

static const int h_m[NLEV]    = {4096,2048,1024,512,256,128,64,32,16,8,4,2,1};
static const int h_l[NLEV]    = {128,128,128,128,128,65,33,17,9,5,3,2,1};
static const int h_toff[NLEV] = {0,524288,786432,917504,983040,1015808,1024128,1026240,1026784,1026928,1026968,1026980,1026984};
static const int h_uoff[NLEV] = {0,4096,6144,7168,7680,7936,8064,8128,8160,8176,8184,8188,8190};

__device__ float g_FC[TAB_TOTAL];
__device__ float g_FS[TAB_TOTAL];
__device__ float g_IC[TAB_TOTAL];
__device__ float g_IS[TAB_TOTAL];

__device__ float g_Wt[6][WSZ];          // [w][f][i*128+o]
__device__ float g_D[SBUF];
__device__ float g_S[2][SBUF];
__device__ float g_UD[BB*CH*8191];
__device__ float g_US[BB*CH*8191];
__device__ float g_VFP[MAXSP*4*VFSZ];   // split-K partials: [sp][arr][b*16384+f*128+o]
__device__ float g_OF[4][VFSZ];         // UDr, UDi, USr, USi

// ---- packed f32x2 helpers ----
__device__ __forceinline__ u64 pk2(float lo, float hi) {
    u64 r; asm("mov.b64 %0, {%1, %2};" : "=l"(r) : "f"(lo), "f"(hi)); return r;
}
__device__ __forceinline__ float2 up2(u64 v) {
    float2 r; asm("mov.b64 {%0, %1}, %2;" : "=f"(r.x), "=f"(r.y) : "l"(v)); return r;
}
__device__ __forceinline__ u64 fma2(u64 a, u64 b, u64 c) {
    u64 d; asm("fma.rn.f32x2 %0, %1, %2, %3;" : "=l"(d) : "l"(a), "l"(b), "l"(c)); return d;
}
__device__ __forceinline__ u64 lds2(const float2& p) {
    return *reinterpret_cast<const u64*>(&p);
}

// ---------------- table init ----------------
__global__ void k_init_tab(int m, int l, int toff) {
    int e = blockIdx.x * blockDim.x + threadIdx.x;
    if (e >= l * m) return;
    int f = e / m, t = e - f * m;
    int p = (int)(((long long)f * t) & (long long)(m - 1));
    float ang = 2.0f * (float)p / (float)m;
    float s, c;
    sincospif(ang, &s, &c);
    g_FC[toff + e] = c;
    g_FS[toff + e] = -s;
    float cf = (f == 0 || 2 * f == m) ? 1.0f : 2.0f;
    float inv = cf / (float)m;
    g_IC[toff + e] = c * inv;
    g_IS[toff + e] = -s * inv;
}

// ---------------- weight transpose ----------------
__global__ void k_wt6(const float* __restrict__ p0, const float* __restrict__ p1,
                      const float* __restrict__ p2, const float* __restrict__ p3,
                      const float* __restrict__ p4, const float* __restrict__ p5) {
    int w = blockIdx.z;
    const float* W = (w == 0) ? p0 : (w == 1) ? p1 : (w == 2) ? p2 : (w == 3) ? p3 : (w == 4) ? p4 : p5;
    __shared__ float tile[32][33];
    int io0 = blockIdx.x * 32, f0 = blockIdx.y * 32;
    int tx = threadIdx.x, ty = threadIdx.y;
    #pragma unroll
    for (int r = ty; r < 32; r += 8)
        tile[r][tx] = W[(io0 + r) * 128 + f0 + tx];
    __syncthreads();
    #pragma unroll
    for (int r = ty; r < 32; r += 8)
        g_Wt[w][(f0 + r) * 16384 + io0 + tx] = tile[tx][r];
}

// ---------------- decompose ----------------
__global__ void k_dec(const float* __restrict__ xin, const float* __restrict__ ecs,
                      const float* __restrict__ ecd, float* __restrict__ dout,
                      float* __restrict__ sout, int m) {
    __shared__ float se[32], sd2[32];
    if (threadIdx.x < 32) { se[threadIdx.x] = ecs[threadIdx.x]; sd2[threadIdx.x] = ecd[threadIdx.x]; }
    __syncthreads();
    int idx = blockIdx.x * blockDim.x + threadIdx.x;
    if (idx >= 16 * m * 32) return;
    int c = idx & 31;
    int bm = idx >> 5;
    int t = bm & (m - 1);
    int b = bm / m;
    long base = ((long)b * 2 * m + 2 * t) * 128 + c * 4;
    float4 xe = *(const float4*)(xin + base);
    float4 xo = *(const float4*)(xin + base + 128);
    float xa[8] = {xe.x, xe.y, xe.z, xe.w, xo.x, xo.y, xo.z, xo.w};
    float dd[4] = {0, 0, 0, 0}, ss[4] = {0, 0, 0, 0};
    #pragma unroll
    for (int j = 0; j < 8; j++) {
        float xv = xa[j];
        #pragma unroll
        for (int k = 0; k < 4; k++) {
            dd[k] = fmaf(xv, sd2[j * 4 + k], dd[k]);
            ss[k] = fmaf(xv, se[j * 4 + k], ss[k]);
        }
    }
    long ob = ((long)b * m + t) * 128 + c * 4;
    *(float4*)(dout + ob) = make_float4(dd[0], dd[1], dd[2], dd[3]);
    *(float4*)(sout + ob) = make_float4(ss[0], ss[1], ss[2], ss[3]);
}

// ---------------- forward partial DFT, split-K, f-tile=128, per-thread 8x4 ----------------
__global__ __launch_bounds__(256) void k_fwd(const float* __restrict__ dsig,
                                             const float* __restrict__ ssig,
                                             float* __restrict__ vfp,
                                             int m, int l, int toff) {
    int sp = blockIdx.z >> 5;
    int zz = blockIdx.z & 31;
    int sig = zz >> 4;
    int b = zz & 15;
    const float* src = sig ? ssig : dsig;
    float* outR = vfp + ((long)(sp * 4 + sig * 2 + 0)) * VFSZ + b * 16384;
    float* outI = vfp + ((long)(sp * 4 + sig * 2 + 1)) * VFSZ + b * 16384;
    int o0 = blockIdx.y * 64;
    int ks = sp * KCHUNK;
    int ke = min(m, ks + KCHUNK);

    __shared__ float2 Acs[8][128];   // (cos, -sin)
    __shared__ float2 Bd[8][64];     // (v, v)
    int tid = threadIdx.x;
    int tx = tid & 15, ty = tid >> 4;
    u64 acc2[8][4];
    #pragma unroll
    for (int i = 0; i < 8; i++)
        #pragma unroll
        for (int j = 0; j < 4; j++) acc2[i][j] = 0;

    for (int kk = ks; kk < ke; kk += 8) {
        #pragma unroll
        for (int p = 0; p < 4; p++) {
            int e = tid + p * 256;
            int tt = e & 7, ff = e >> 3;
            float ac = 0.f, as = 0.f;
            int t = kk + tt;
            if (ff < l && t < m) { int a = toff + ff * m + t; ac = g_FC[a]; as = g_FS[a]; }
            Acs[tt][ff] = make_float2(ac, as);
        }
        #pragma unroll
        for (int p = 0; p < 2; p++) {
            int e = tid + p * 256;
            int oo = e & 63, tt = e >> 6;
            float v = 0.f;
            int t = kk + tt;
            if (t < m) v = src[((long)b * m + t) * 128 + o0 + oo];
            Bd[tt][oo] = make_float2(v, v);
        }
        __syncthreads();
        #pragma unroll
        for (int k = 0; k < 8; k++) {
            u64 a2[8], b2[4];
            #pragma unroll
            for (int i = 0; i < 8; i++) a2[i] = lds2(Acs[k][ty * 8 + i]);
            #pragma unroll
            for (int j = 0; j < 4; j++) b2[j] = lds2(Bd[k][tx * 4 + j]);
            #pragma unroll
            for (int i = 0; i < 8; i++)
                #pragma unroll
                for (int j = 0; j < 4; j++)
                    acc2[i][j] = fma2(a2[i], b2[j], acc2[i][j]);
        }
        __syncthreads();
    }
    #pragma unroll
    for (int i = 0; i < 8; i++) {
        int f = ty * 8 + i;
        if (f < l) {
            #pragma unroll
            for (int j = 0; j < 4; j++) {
                int o = o0 + tx * 4 + j;
                float2 cs = up2(acc2[i][j]);
                outR[f * 128 + o] = cs.x;
                outI[f * 128 + o] = cs.y;
            }
        }
    }
}

// ---------------- fused mode mix: UD = A(Vd)+B(Vs), US = C(Vd); sums split-K partials ----------------
__global__ __launch_bounds__(128) void k_mix2(const float* __restrict__ Wt,
                                              const float* __restrict__ vfp, int nsp,
                                              float* __restrict__ UDr, float* __restrict__ UDi,
                                              float* __restrict__ USr, float* __restrict__ USi) {
    int f = blockIdx.x;
    int half = blockIdx.y;
    int o = threadIdx.x;
    const float* WAr = Wt + 0 * WSZ + f * 16384;
    const float* WAi = Wt + 1 * WSZ + f * 16384;
    const float* WBr = Wt + 2 * WSZ + f * 16384;
    const float* WBi = Wt + 3 * WSZ + f * 16384;
    const float* WCr = Wt + 4 * WSZ + f * 16384;
    const float* WCi = Wt + 5 * WSZ + f * 16384;
    __shared__ float4 sX[128][4];
    __shared__ float4 sNY[128][4];
    u64 aUD[8], aUS[8];
    #pragma unroll
    for (int q = 0; q < 8; q++) { aUD[q] = 0; aUS[q] = 0; }

    // ---- pass 1: Vd (arrs 0,1) -> W_A into UD, W_C into US
    {
        float vx[8], vy[8];
        #pragma unroll
        for (int jj = 0; jj < 8; jj++) {
            int j = half * 8 + jj;
            float sx = 0.f, sy = 0.f;
            for (int sp = 0; sp < nsp; sp++) {
                sx += vfp[((long)(sp * 4 + 0)) * VFSZ + j * 16384 + f * 128 + o];
                sy += vfp[((long)(sp * 4 + 1)) * VFSZ + j * 16384 + f * 128 + o];
            }
            vx[jj] = sx; vy[jj] = sy;
        }
        #pragma unroll
        for (int bp = 0; bp < 4; bp++) {
            sX[o][bp]  = make_float4(vx[2 * bp], vx[2 * bp], vx[2 * bp + 1], vx[2 * bp + 1]);
            sNY[o][bp] = make_float4(-vy[2 * bp], vy[2 * bp], -vy[2 * bp + 1], vy[2 * bp + 1]);
        }
    }
    __syncthreads();
    for (int i = 0; i < 128; i++) {
        float war = WAr[i * 128 + o], wai = WAi[i * 128 + o];
        float wcr = WCr[i * 128 + o], wci = WCi[i * 128 + o];
        u64 wAri = pk2(war, wai), wAir = pk2(wai, war);
        u64 wCri = pk2(wcr, wci), wCir = pk2(wci, wcr);
        #pragma unroll
        for (int bp = 0; bp < 4; bp++) {
            float4 X = sX[i][bp]; float4 NY = sNY[i][bp];
            u64 x0 = *(u64*)&X.x, x1 = *(u64*)&X.z;
            u64 n0 = *(u64*)&NY.x, n1 = *(u64*)&NY.z;
            aUD[2 * bp]     = fma2(x0, wAri, aUD[2 * bp]);
            aUD[2 * bp]     = fma2(n0, wAir, aUD[2 * bp]);
            aUD[2 * bp + 1] = fma2(x1, wAri, aUD[2 * bp + 1]);
            aUD[2 * bp + 1] = fma2(n1, wAir, aUD[2 * bp + 1]);
            aUS[2 * bp]     = fma2(x0, wCri, aUS[2 * bp]);
            aUS[2 * bp]     = fma2(n0, wCir, aUS[2 * bp]);
            aUS[2 * bp + 1] = fma2(x1, wCri, aUS[2 * bp + 1]);
            aUS[2 * bp + 1] = fma2(n1, wCir, aUS[2 * bp + 1]);
        }
    }
    __syncthreads();
    // ---- pass 2: Vs (arrs 2,3) -> W_B into UD
    {
        float vx[8], vy[8];
        #pragma unroll
        for (int jj = 0; jj < 8; jj++) {
            int j = half * 8 + jj;
            float sx = 0.f, sy = 0.f;
            for (int sp = 0; sp < nsp; sp++) {
                sx += vfp[((long)(sp * 4 + 2)) * VFSZ + j * 16384 + f * 128 + o];
                sy += vfp[((long)(sp * 4 + 3)) * VFSZ + j * 16384 + f * 128 + o];
            }
            vx[jj] = sx; vy[jj] = sy;
        }
        #pragma unroll
        for (int bp = 0; bp < 4; bp++) {
            sX[o][bp]  = make_float4(vx[2 * bp], vx[2 * bp], vx[2 * bp + 1], vx[2 * bp + 1]);
            sNY[o][bp] = make_float4(-vy[2 * bp], vy[2 * bp], -vy[2 * bp + 1], vy[2 * bp + 1]);
        }
    }
    __syncthreads();
    for (int i = 0; i < 128; i++) {
        float wbr = WBr[i * 128 + o], wbi = WBi[i * 128 + o];
        u64 wBri = pk2(wbr, wbi), wBir = pk2(wbi, wbr);
        #pragma unroll
        for (int bp = 0; bp < 4; bp++) {
            float4 X = sX[i][bp]; float4 NY = sNY[i][bp];
            u64 x0 = *(u64*)&X.x, x1 = *(u64*)&X.z;
            u64 n0 = *(u64*)&NY.x, n1 = *(u64*)&NY.z;
            aUD[2 * bp]     = fma2(x0, wBri, aUD[2 * bp]);
            aUD[2 * bp]     = fma2(n0, wBir, aUD[2 * bp]);
            aUD[2 * bp + 1] = fma2(x1, wBri, aUD[2 * bp + 1]);
            aUD[2 * bp + 1] = fma2(n1, wBir, aUD[2 * bp + 1]);
        }
    }
    #pragma unroll
    for (int jj = 0; jj < 8; jj++) {
        int j = half * 8 + jj;
        float2 d = up2(aUD[jj]);
        float2 s = up2(aUS[jj]);
        UDr[j * 16384 + f * 128 + o] = d.x;
        UDi[j * 16384 + f * 128 + o] = d.y;
        USr[j * 16384 + f * 128 + o] = s.x;
        USi[j * 16384 + f * 128 + o] = s.y;
    }
}

// ---------------- inverse partial DFT, UD+US fused (shared A tiles), per-thread 8x4x2 ----------------
__global__ __launch_bounds__(256) void k_inv(float* __restrict__ outUD, float* __restrict__ outUS,
                                             const float* __restrict__ of,
                                             int m, int l, int toff) {
    int b = blockIdx.z;
    int t0 = blockIdx.x * 128;
    int o0 = blockIdx.y * 64;
    __shared__ float2 Acd[8][128];   // (ic, ic)
    __shared__ float2 Asd[8][128];   // (is, is)
    __shared__ float sB[4][8][64];   // UDr, UDi, USr, USi
    int tid = threadIdx.x;
    int tx = tid & 15, ty = tid >> 4;
    u64 aUD[8][2], aUS[8][2];
    #pragma unroll
    for (int i = 0; i < 8; i++)
        #pragma unroll
        for (int j = 0; j < 2; j++) { aUD[i][j] = 0; aUS[i][j] = 0; }

    for (int kk = 0; kk < l; kk += 8) {
        #pragma unroll
        for (int p = 0; p < 4; p++) {
            int e = tid + p * 256;
            int tt = e & 127, kr = e >> 7;
            float ac = 0.f, as = 0.f;
            int f = kk + kr, t = t0 + tt;
            if (f < l && t < m) { int a = toff + f * m + t; ac = g_IC[a]; as = g_IS[a]; }
            Acd[kr][tt] = make_float2(ac, ac);
            Asd[kr][tt] = make_float2(as, as);
        }
        #pragma unroll
        for (int p = 0; p < 8; p++) {
            int e = tid + p * 256;
            int arr = e >> 9;
            int r = e & 511;
            int kr = r >> 6, oo = r & 63;
            int f = kk + kr;
            float v = 0.f;
            if (f < l) v = of[(long)arr * VFSZ + b * 16384 + f * 128 + o0 + oo];
            sB[arr][kr][oo] = v;
        }
        __syncthreads();
        #pragma unroll
        for (int k = 0; k < 8; k++) {
            u64 ac[8], as_[8];
            #pragma unroll
            for (int i = 0; i < 8; i++) { ac[i] = lds2(Acd[k][ty * 8 + i]); as_[i] = lds2(Asd[k][ty * 8 + i]); }
            u64 b0r[2], b0i[2], b1r[2], b1i[2];
            #pragma unroll
            for (int j = 0; j < 2; j++) {
                b0r[j] = *(const u64*)&sB[0][k][tx * 4 + 2 * j];
                b0i[j] = *(const u64*)&sB[1][k][tx * 4 + 2 * j];
                b1r[j] = *(const u64*)&sB[2][k][tx * 4 + 2 * j];
                b1i[j] = *(const u64*)&sB[3][k][tx * 4 + 2 * j];
            }
            #pragma unroll
            for (int i = 0; i < 8; i++)
                #pragma unroll
                for (int j = 0; j < 2; j++) {
                    aUD[i][j] = fma2(ac[i], b0r[j], aUD[i][j]);
                    aUD[i][j] = fma2(as_[i], b0i[j], aUD[i][j]);
                    aUS[i][j] = fma2(ac[i], b1r[j], aUS[i][j]);
                    aUS[i][j] = fma2(as_[i], b1i[j], aUS[i][j]);
                }
        }
        __syncthreads();
    }
    #pragma unroll
    for (int i = 0; i < 8; i++) {
        int t = t0 + ty * 8 + i;
        if (t < m) {
            long ob = ((long)b * m + t) * 128 + o0 + tx * 4;
            float2 p0 = up2(aUD[i][0]), p1 = up2(aUD[i][1]);
            *(float4*)(outUD + ob) = make_float4(p0.x, p0.y, p1.x, p1.y);
            float2 q0 = up2(aUS[i][0]), q1 = up2(aUS[i][1]);
            *(float4*)(outUS + ob) = make_float4(q0.x, q0.y, q1.x, q1.y);
        }
    }
}

// ---------------- coarsest T0 ----------------
__global__ void k_t0(const float* __restrict__ xin, const float* __restrict__ w,
                     const float* __restrict__ bias, float* __restrict__ xout) {
    int idx = blockIdx.x * blockDim.x + threadIdx.x;
    if (idx >= 512) return;
    float4 xv = *(const float4*)(xin + idx * 4);
    float xa[4] = {xv.x, xv.y, xv.z, xv.w};
    float y[4];
    #pragma unroll
    for (int k = 0; k < 4; k++) {
        float acc = bias[k];
        #pragma unroll
        for (int j = 0; j < 4; j++) acc = fmaf(xa[j], w[k * 4 + j], acc);
        y[k] = acc;
    }
    *(float4*)(xout + idx * 4) = make_float4(y[0], y[1], y[2], y[3]);
}

// ---------------- reconstruct ----------------
__global__ void k_rec(const float* __restrict__ xin, const float* __restrict__ ud,
                      const float* __restrict__ us, const float* __restrict__ rce,
                      const float* __restrict__ rco, float* __restrict__ xout, int m) {
    __shared__ float se[32], so[32];
    if (threadIdx.x < 32) { se[threadIdx.x] = rce[threadIdx.x]; so[threadIdx.x] = rco[threadIdx.x]; }
    __syncthreads();
    int idx = blockIdx.x * blockDim.x + threadIdx.x;
    if (idx >= 16 * m * 32) return;
    int c = idx & 31;
    int bm = idx >> 5;
    int t = bm & (m - 1);
    int b = bm / m;
    long ib = ((long)b * m + t) * 128 + c * 4;
    float4 xv = *(const float4*)(xin + ib);
    float4 uv = *(const float4*)(us + ib);
    float4 dv = *(const float4*)(ud + ib);
    float xx[8] = {xv.x + uv.x, xv.y + uv.y, xv.z + uv.z, xv.w + uv.w, dv.x, dv.y, dv.z, dv.w};
    float xe[4] = {0, 0, 0, 0}, xo[4] = {0, 0, 0, 0};
    #pragma unroll
    for (int j = 0; j < 8; j++) {
        float xj = xx[j];
        #pragma unroll
        for (int k = 0; k < 4; k++) {
            xe[k] = fmaf(xj, se[j * 4 + k], xe[k]);
            xo[k] = fmaf(xj, so[j * 4 + k], xo[k]);
        }
    }
    long ob = ((long)b * 2 * m + 2 * t) * 128 + c * 4;
    *(float4*)(xout + ob) = make_float4(xe[0], xe[1], xe[2], xe[3]);
    *(float4*)(xout + ob + 128) = make_float4(xo[0], xo[1], xo[2], xo[3]);
}

extern "C" void kernel_launch(void* const* d_in, const int* in_sizes, int n_in,
                              void* d_out, int out_size) {
    const float* x = (const float*)d_in[0];
    const float* W6[6];
    for (int i = 0; i < 6; i++) W6[i] = (const float*)d_in[1 + i];
    const float* small32[4] = {0, 0, 0, 0};
    const float* T0w = 0; const float* T0b = 0;
    int n32 = 0;
    for (int i = 7; i < n_in; i++) {
        int s = in_sizes[i];
        if (s == 32 && n32 < 4) small32[n32++] = (const float*)d_in[i];
        else if (s == 16) T0w = (const float*)d_in[i];
        else if (s == 4) T0b = (const float*)d_in[i];
    }
    const float* ec_s = small32[0];
    const float* ec_d = small32[1];
    const float* rc_e = small32[2];
    const float* rc_o = small32[3];

    float *pD, *pS, *pUD, *pUS, *pVFP, *pOF, *pWt;
    cudaGetSymbolAddress((void**)&pD, g_D);
    cudaGetSymbolAddress((void**)&pS, g_S);
    cudaGetSymbolAddress((void**)&pUD, g_UD);
    cudaGetSymbolAddress((void**)&pUS, g_US);
    cudaGetSymbolAddress((void**)&pVFP, g_VFP);
    cudaGetSymbolAddress((void**)&pOF, g_OF);
    cudaGetSymbolAddress((void**)&pWt, g_Wt);
    float* pS0 = pS;
    float* pS1 = pS + SBUF;

    for (int i = 0; i < NLEV; i++) {
        int tot = h_l[i] * h_m[i];
        k_init_tab<<<(tot + 255) / 256, 256>>>(h_m[i], h_l[i], h_toff[i]);
    }
    {
        dim3 g(512, 4, 6);
        k_wt6<<<g, dim3(32, 8)>>>(W6[0], W6[1], W6[2], W6[3], W6[4], W6[5]);
    }

    const float* xin = x;
    for (int i = 0; i < NLEV; i++) {
        int m = h_m[i], l = h_l[i], toff = h_toff[i];
        int nsp = (m >= KCHUNK) ? (m / KCHUNK) : 1;
        float* sout = (i & 1) ? pS1 : pS0;
        int tot = BB * m * 32;
        k_dec<<<(tot + 255) / 256, 256>>>(xin, ec_s, ec_d, pD, sout, m);
        dim3 gf(1, 2, 32 * nsp);
        k_fwd<<<gf, 256>>>(pD, sout, pVFP, m, l, toff);
        dim3 gm(l, 2);
        k_mix2<<<gm, 128>>>(pWt, pVFP, nsp,
                            pOF + 0 * VFSZ, pOF + 1 * VFSZ,
                            pOF + 2 * VFSZ, pOF + 3 * VFSZ);
        dim3 gi((m + 127) / 128, 2, 16);
        k_inv<<<gi, 256>>>(pUD + (long)h_uoff[i] * (BB * CH),
                           pUS + (long)h_uoff[i] * (BB * CH),
                           pOF, m, l, toff);
        xin = sout;
    }

    k_t0<<<2, 256>>>(pS0, T0w, T0b, pS1);

    float* rin = pS1;
    for (int i = NLEV - 1; i >= 0; i--) {
        int m = h_m[i];
        float* rout = (i == 0) ? (float*)d_out : ((rin == pS1) ? pS0 : pS1);
        int tot = BB * m * 32;
        k_rec<<<(tot + 255) / 256, 256>>>(rin,
                                          pUD + (long)h_uoff[i] * (BB * CH),
                                          pUS + (long)h_uoff[i] * (BB * CH),
                                          rc_e, rc_o, rout, m);
        rin = rout;
    }
}

// round 11
// speedup vs baseline: 1.5835x; 1.0792x over previous
#include <cuda_runtime.h>
#include <math.h>

#define BB 16
#define CH 128
#define NLEV 13
#define VFSZ (BB*128*CH)     // 262144
#define WSZ  (128*128*128)   // 2097152
#define TAB_TOTAL 1026985
#define SBUF (BB*4096*CH)    // 8388608
#define MAXSP 8
#define KCHUNK 512

typedef unsigned long long u64;

static const int h_m[NLEV]    = {4096,2048,1024,512,256,128,64,32,16,8,4,2,1};
static const int h_l[NLEV]    = {128,128,128,128,128,65,33,17,9,5,3,2,1};
static const int h_toff[NLEV] = {0,524288,786432,917504,983040,1015808,1024128,1026240,1026784,1026928,1026968,1026980,1026984};
static const int h_uoff[NLEV] = {0,4096,6144,7168,7680,7936,8064,8128,8160,8176,8184,8188,8190};

__device__ float g_FC[TAB_TOTAL];
__device__ float g_FS[TAB_TOTAL];
__device__ float g_IC[TAB_TOTAL];
__device__ float g_IS[TAB_TOTAL];

__device__ float g_Wt[6][WSZ];          // [w][f][i*128+o]
__device__ float g_D[SBUF];
__device__ float g_S[2][SBUF];
__device__ float g_UD[BB*CH*8191];
__device__ float g_US[BB*CH*8191];
__device__ float g_VFP[MAXSP*4*VFSZ];   // split-K partials
__device__ float g_OF[4][VFSZ];         // UDr, UDi, USr, USi

// ---- packed f32x2 helpers ----
__device__ __forceinline__ u64 pk2(float lo, float hi) {
    u64 r; asm("mov.b64 %0, {%1, %2};" : "=l"(r) : "f"(lo), "f"(hi)); return r;
}
__device__ __forceinline__ float2 up2(u64 v) {
    float2 r; asm("mov.b64 {%0, %1}, %2;" : "=f"(r.x), "=f"(r.y) : "l"(v)); return r;
}
__device__ __forceinline__ u64 fma2(u64 a, u64 b, u64 c) {
    u64 d; asm("fma.rn.f32x2 %0, %1, %2, %3;" : "=l"(d) : "l"(a), "l"(b), "l"(c)); return d;
}
__device__ __forceinline__ u64 lds2(const float2& p) {
    return *reinterpret_cast<const u64*>(&p);
}

// ---------------- table init: single launch covering all levels ----------------
__global__ void k_init_tab_all() {
    const int toff[NLEV + 1] = {0,524288,786432,917504,983040,1015808,1024128,1026240,1026784,1026928,1026968,1026980,1026984,1026985};
    const int mm[NLEV] = {4096,2048,1024,512,256,128,64,32,16,8,4,2,1};
    for (int e = blockIdx.x * blockDim.x + threadIdx.x; e < TAB_TOTAL; e += gridDim.x * blockDim.x) {
        int lev = 0;
        #pragma unroll
        for (int i = 1; i < NLEV; i++)
            if (e >= toff[i]) lev = i;
        int m = mm[lev];
        int r = e - toff[lev];
        int f = r / m, t = r - f * m;
        int p = (int)(((long long)f * t) & (long long)(m - 1));
        float ang = 2.0f * (float)p / (float)m;
        float s, c;
        sincospif(ang, &s, &c);
        g_FC[e] = c;
        g_FS[e] = -s;
        float cf = (f == 0 || 2 * f == m) ? 1.0f : 2.0f;
        float inv = cf / (float)m;
        g_IC[e] = c * inv;
        g_IS[e] = -s * inv;
    }
}

// ---------------- weight transpose ----------------
__global__ void k_wt6(const float* __restrict__ p0, const float* __restrict__ p1,
                      const float* __restrict__ p2, const float* __restrict__ p3,
                      const float* __restrict__ p4, const float* __restrict__ p5) {
    int w = blockIdx.z;
    const float* W = (w == 0) ? p0 : (w == 1) ? p1 : (w == 2) ? p2 : (w == 3) ? p3 : (w == 4) ? p4 : p5;
    __shared__ float tile[32][33];
    int io0 = blockIdx.x * 32, f0 = blockIdx.y * 32;
    int tx = threadIdx.x, ty = threadIdx.y;
    #pragma unroll
    for (int r = ty; r < 32; r += 8)
        tile[r][tx] = W[(io0 + r) * 128 + f0 + tx];
    __syncthreads();
    #pragma unroll
    for (int r = ty; r < 32; r += 8)
        g_Wt[w][(f0 + r) * 16384 + io0 + tx] = tile[tx][r];
}

// ---------------- decompose ----------------
__global__ void k_dec(const float* __restrict__ xin, const float* __restrict__ ecs,
                      const float* __restrict__ ecd, float* __restrict__ dout,
                      float* __restrict__ sout, int m) {
    __shared__ float se[32], sd2[32];
    if (threadIdx.x < 32) { se[threadIdx.x] = ecs[threadIdx.x]; sd2[threadIdx.x] = ecd[threadIdx.x]; }
    __syncthreads();
    int idx = blockIdx.x * blockDim.x + threadIdx.x;
    if (idx >= 16 * m * 32) return;
    int c = idx & 31;
    int bm = idx >> 5;
    int t = bm & (m - 1);
    int b = bm / m;
    long base = ((long)b * 2 * m + 2 * t) * 128 + c * 4;
    float4 xe = *(const float4*)(xin + base);
    float4 xo = *(const float4*)(xin + base + 128);
    float xa[8] = {xe.x, xe.y, xe.z, xe.w, xo.x, xo.y, xo.z, xo.w};
    float dd[4] = {0, 0, 0, 0}, ss[4] = {0, 0, 0, 0};
    #pragma unroll
    for (int j = 0; j < 8; j++) {
        float xv = xa[j];
        #pragma unroll
        for (int k = 0; k < 4; k++) {
            dd[k] = fmaf(xv, sd2[j * 4 + k], dd[k]);
            ss[k] = fmaf(xv, se[j * 4 + k], ss[k]);
        }
    }
    long ob = ((long)b * m + t) * 128 + c * 4;
    *(float4*)(dout + ob) = make_float4(dd[0], dd[1], dd[2], dd[3]);
    *(float4*)(sout + ob) = make_float4(ss[0], ss[1], ss[2], ss[3]);
}

// ---------------- forward partial DFT, split-K, conflict-free B loads ----------------
__global__ __launch_bounds__(256) void k_fwd(const float* __restrict__ dsig,
                                             const float* __restrict__ ssig,
                                             float* __restrict__ vfp,
                                             int m, int l, int toff) {
    int sp = blockIdx.z >> 5;
    int zz = blockIdx.z & 31;
    int sig = zz >> 4;
    int b = zz & 15;
    const float* src = sig ? ssig : dsig;
    float* outR = vfp + ((long)(sp * 4 + sig * 2 + 0)) * VFSZ + b * 16384;
    float* outI = vfp + ((long)(sp * 4 + sig * 2 + 1)) * VFSZ + b * 16384;
    int o0 = blockIdx.y * 64;
    int ks = sp * KCHUNK;
    int ke = min(m, ks + KCHUNK);

    __shared__ float2 Acs[8][128];   // (cos, -sin)
    __shared__ float2 Bd[8][64];     // (v, v)
    int tid = threadIdx.x;
    int tx = tid & 15, ty = tid >> 4;
    u64 acc2[8][4];
    #pragma unroll
    for (int i = 0; i < 8; i++)
        #pragma unroll
        for (int j = 0; j < 4; j++) acc2[i][j] = 0;

    for (int kk = ks; kk < ke; kk += 8) {
        #pragma unroll
        for (int p = 0; p < 4; p++) {
            int e = tid + p * 256;
            int tt = e & 7, ff = e >> 3;
            float ac = 0.f, as = 0.f;
            int t = kk + tt;
            if (ff < l && t < m) { int a = toff + ff * m + t; ac = g_FC[a]; as = g_FS[a]; }
            Acs[tt][ff] = make_float2(ac, as);
        }
        #pragma unroll
        for (int p = 0; p < 2; p++) {
            int e = tid + p * 256;
            int oo = e & 63, tt = e >> 6;
            float v = 0.f;
            int t = kk + tt;
            if (t < m) v = src[((long)b * m + t) * 128 + o0 + oo];
            Bd[tt][oo] = make_float2(v, v);
        }
        __syncthreads();
        #pragma unroll
        for (int k = 0; k < 8; k++) {
            u64 a2[8], b2[4];
            #pragma unroll
            for (int i = 0; i < 8; i++) a2[i] = lds2(Acs[k][ty * 8 + i]);
            #pragma unroll
            for (int j = 0; j < 4; j++) b2[j] = lds2(Bd[k][j * 16 + tx]);   // conflict-free
            #pragma unroll
            for (int i = 0; i < 8; i++)
                #pragma unroll
                for (int j = 0; j < 4; j++)
                    acc2[i][j] = fma2(a2[i], b2[j], acc2[i][j]);
        }
        __syncthreads();
    }
    #pragma unroll
    for (int i = 0; i < 8; i++) {
        int f = ty * 8 + i;
        if (f < l) {
            #pragma unroll
            for (int j = 0; j < 4; j++) {
                int o = o0 + j * 16 + tx;
                float2 cs = up2(acc2[i][j]);
                outR[f * 128 + o] = cs.x;
                outI[f * 128 + o] = cs.y;
            }
        }
    }
}

// ---------------- fused mode mix ----------------
__global__ __launch_bounds__(128) void k_mix2(const float* __restrict__ Wt,
                                              const float* __restrict__ vfp, int nsp,
                                              float* __restrict__ UDr, float* __restrict__ UDi,
                                              float* __restrict__ USr, float* __restrict__ USi) {
    int f = blockIdx.x;
    int half = blockIdx.y;
    int o = threadIdx.x;
    const float* WAr = Wt + 0 * WSZ + f * 16384;
    const float* WAi = Wt + 1 * WSZ + f * 16384;
    const float* WBr = Wt + 2 * WSZ + f * 16384;
    const float* WBi = Wt + 3 * WSZ + f * 16384;
    const float* WCr = Wt + 4 * WSZ + f * 16384;
    const float* WCi = Wt + 5 * WSZ + f * 16384;
    __shared__ float4 sX[128][4];
    __shared__ float4 sNY[128][4];
    u64 aUD[8], aUS[8];
    #pragma unroll
    for (int q = 0; q < 8; q++) { aUD[q] = 0; aUS[q] = 0; }

    {
        float vx[8], vy[8];
        #pragma unroll
        for (int jj = 0; jj < 8; jj++) {
            int j = half * 8 + jj;
            float sx = 0.f, sy = 0.f;
            for (int sp = 0; sp < nsp; sp++) {
                sx += vfp[((long)(sp * 4 + 0)) * VFSZ + j * 16384 + f * 128 + o];
                sy += vfp[((long)(sp * 4 + 1)) * VFSZ + j * 16384 + f * 128 + o];
            }
            vx[jj] = sx; vy[jj] = sy;
        }
        #pragma unroll
        for (int bp = 0; bp < 4; bp++) {
            sX[o][bp]  = make_float4(vx[2 * bp], vx[2 * bp], vx[2 * bp + 1], vx[2 * bp + 1]);
            sNY[o][bp] = make_float4(-vy[2 * bp], vy[2 * bp], -vy[2 * bp + 1], vy[2 * bp + 1]);
        }
    }
    __syncthreads();
    for (int i = 0; i < 128; i++) {
        float war = WAr[i * 128 + o], wai = WAi[i * 128 + o];
        float wcr = WCr[i * 128 + o], wci = WCi[i * 128 + o];
        u64 wAri = pk2(war, wai), wAir = pk2(wai, war);
        u64 wCri = pk2(wcr, wci), wCir = pk2(wci, wcr);
        #pragma unroll
        for (int bp = 0; bp < 4; bp++) {
            float4 X = sX[i][bp]; float4 NY = sNY[i][bp];
            u64 x0 = *(u64*)&X.x, x1 = *(u64*)&X.z;
            u64 n0 = *(u64*)&NY.x, n1 = *(u64*)&NY.z;
            aUD[2 * bp]     = fma2(x0, wAri, aUD[2 * bp]);
            aUD[2 * bp]     = fma2(n0, wAir, aUD[2 * bp]);
            aUD[2 * bp + 1] = fma2(x1, wAri, aUD[2 * bp + 1]);
            aUD[2 * bp + 1] = fma2(n1, wAir, aUD[2 * bp + 1]);
            aUS[2 * bp]     = fma2(x0, wCri, aUS[2 * bp]);
            aUS[2 * bp]     = fma2(n0, wCir, aUS[2 * bp]);
            aUS[2 * bp + 1] = fma2(x1, wCri, aUS[2 * bp + 1]);
            aUS[2 * bp + 1] = fma2(n1, wCir, aUS[2 * bp + 1]);
        }
    }
    __syncthreads();
    {
        float vx[8], vy[8];
        #pragma unroll
        for (int jj = 0; jj < 8; jj++) {
            int j = half * 8 + jj;
            float sx = 0.f, sy = 0.f;
            for (int sp = 0; sp < nsp; sp++) {
                sx += vfp[((long)(sp * 4 + 2)) * VFSZ + j * 16384 + f * 128 + o];
                sy += vfp[((long)(sp * 4 + 3)) * VFSZ + j * 16384 + f * 128 + o];
            }
            vx[jj] = sx; vy[jj] = sy;
        }
        #pragma unroll
        for (int bp = 0; bp < 4; bp++) {
            sX[o][bp]  = make_float4(vx[2 * bp], vx[2 * bp], vx[2 * bp + 1], vx[2 * bp + 1]);
            sNY[o][bp] = make_float4(-vy[2 * bp], vy[2 * bp], -vy[2 * bp + 1], vy[2 * bp + 1]);
        }
    }
    __syncthreads();
    for (int i = 0; i < 128; i++) {
        float wbr = WBr[i * 128 + o], wbi = WBi[i * 128 + o];
        u64 wBri = pk2(wbr, wbi), wBir = pk2(wbi, wbr);
        #pragma unroll
        for (int bp = 0; bp < 4; bp++) {
            float4 X = sX[i][bp]; float4 NY = sNY[i][bp];
            u64 x0 = *(u64*)&X.x, x1 = *(u64*)&X.z;
            u64 n0 = *(u64*)&NY.x, n1 = *(u64*)&NY.z;
            aUD[2 * bp]     = fma2(x0, wBri, aUD[2 * bp]);
            aUD[2 * bp]     = fma2(n0, wBir, aUD[2 * bp]);
            aUD[2 * bp + 1] = fma2(x1, wBri, aUD[2 * bp + 1]);
            aUD[2 * bp + 1] = fma2(n1, wBir, aUD[2 * bp + 1]);
        }
    }
    #pragma unroll
    for (int jj = 0; jj < 8; jj++) {
        int j = half * 8 + jj;
        float2 d = up2(aUD[jj]);
        float2 s = up2(aUS[jj]);
        UDr[j * 16384 + f * 128 + o] = d.x;
        UDi[j * 16384 + f * 128 + o] = d.y;
        USr[j * 16384 + f * 128 + o] = s.x;
        USi[j * 16384 + f * 128 + o] = s.y;
    }
}

// ---------------- inverse partial DFT, conflict-free B loads ----------------
__global__ __launch_bounds__(256) void k_inv(float* __restrict__ outUD, float* __restrict__ outUS,
                                             const float* __restrict__ of,
                                             int m, int l, int toff) {
    int b = blockIdx.z;
    int t0 = blockIdx.x * 128;
    int o0 = blockIdx.y * 64;
    __shared__ float2 Acd[8][128];
    __shared__ float2 Asd[8][128];
    __shared__ float sB[4][8][64];
    int tid = threadIdx.x;
    int tx = tid & 15, ty = tid >> 4;
    u64 aUD[8][2], aUS[8][2];
    #pragma unroll
    for (int i = 0; i < 8; i++)
        #pragma unroll
        for (int j = 0; j < 2; j++) { aUD[i][j] = 0; aUS[i][j] = 0; }

    for (int kk = 0; kk < l; kk += 8) {
        #pragma unroll
        for (int p = 0; p < 4; p++) {
            int e = tid + p * 256;
            int tt = e & 127, kr = e >> 7;
            float ac = 0.f, as = 0.f;
            int f = kk + kr, t = t0 + tt;
            if (f < l && t < m) { int a = toff + f * m + t; ac = g_IC[a]; as = g_IS[a]; }
            Acd[kr][tt] = make_float2(ac, ac);
            Asd[kr][tt] = make_float2(as, as);
        }
        #pragma unroll
        for (int p = 0; p < 8; p++) {
            int e = tid + p * 256;
            int arr = e >> 9;
            int r = e & 511;
            int kr = r >> 6, oo = r & 63;
            int f = kk + kr;
            float v = 0.f;
            if (f < l) v = of[(long)arr * VFSZ + b * 16384 + f * 128 + o0 + oo];
            sB[arr][kr][oo] = v;
        }
        __syncthreads();
        #pragma unroll
        for (int k = 0; k < 8; k++) {
            u64 ac[8], as_[8];
            #pragma unroll
            for (int i = 0; i < 8; i++) { ac[i] = lds2(Acd[k][ty * 8 + i]); as_[i] = lds2(Asd[k][ty * 8 + i]); }
            u64 b0r[2], b0i[2], b1r[2], b1i[2];
            #pragma unroll
            for (int j = 0; j < 2; j++) {
                b0r[j] = *(const u64*)&sB[0][k][j * 32 + tx * 2];   // conflict-free
                b0i[j] = *(const u64*)&sB[1][k][j * 32 + tx * 2];
                b1r[j] = *(const u64*)&sB[2][k][j * 32 + tx * 2];
                b1i[j] = *(const u64*)&sB[3][k][j * 32 + tx * 2];
            }
            #pragma unroll
            for (int i = 0; i < 8; i++)
                #pragma unroll
                for (int j = 0; j < 2; j++) {
                    aUD[i][j] = fma2(ac[i], b0r[j], aUD[i][j]);
                    aUD[i][j] = fma2(as_[i], b0i[j], aUD[i][j]);
                    aUS[i][j] = fma2(ac[i], b1r[j], aUS[i][j]);
                    aUS[i][j] = fma2(as_[i], b1i[j], aUS[i][j]);
                }
        }
        __syncthreads();
    }
    #pragma unroll
    for (int i = 0; i < 8; i++) {
        int t = t0 + ty * 8 + i;
        if (t < m) {
            long ob = ((long)b * m + t) * 128 + o0;
            #pragma unroll
            for (int j = 0; j < 2; j++) {
                float2 pd = up2(aUD[i][j]);
                float2 ps = up2(aUS[i][j]);
                *(float2*)(outUD + ob + j * 32 + tx * 2) = pd;
                *(float2*)(outUS + ob + j * 32 + tx * 2) = ps;
            }
        }
    }
}

// ---------------- coarsest T0 ----------------
__global__ void k_t0(const float* __restrict__ xin, const float* __restrict__ w,
                     const float* __restrict__ bias, float* __restrict__ xout) {
    int idx = blockIdx.x * blockDim.x + threadIdx.x;
    if (idx >= 512) return;
    float4 xv = *(const float4*)(xin + idx * 4);
    float xa[4] = {xv.x, xv.y, xv.z, xv.w};
    float y[4];
    #pragma unroll
    for (int k = 0; k < 4; k++) {
        float acc = bias[k];
        #pragma unroll
        for (int j = 0; j < 4; j++) acc = fmaf(xa[j], w[k * 4 + j], acc);
        y[k] = acc;
    }
    *(float4*)(xout + idx * 4) = make_float4(y[0], y[1], y[2], y[3]);
}

// ---------------- reconstruct ----------------
__global__ void k_rec(const float* __restrict__ xin, const float* __restrict__ ud,
                      const float* __restrict__ us, const float* __restrict__ rce,
                      const float* __restrict__ rco, float* __restrict__ xout, int m) {
    __shared__ float se[32], so[32];
    if (threadIdx.x < 32) { se[threadIdx.x] = rce[threadIdx.x]; so[threadIdx.x] = rco[threadIdx.x]; }
    __syncthreads();
    int idx = blockIdx.x * blockDim.x + threadIdx.x;
    if (idx >= 16 * m * 32) return;
    int c = idx & 31;
    int bm = idx >> 5;
    int t = bm & (m - 1);
    int b = bm / m;
    long ib = ((long)b * m + t) * 128 + c * 4;
    float4 xv = *(const float4*)(xin + ib);
    float4 uv = *(const float4*)(us + ib);
    float4 dv = *(const float4*)(ud + ib);
    float xx[8] = {xv.x + uv.x, xv.y + uv.y, xv.z + uv.z, xv.w + uv.w, dv.x, dv.y, dv.z, dv.w};
    float xe[4] = {0, 0, 0, 0}, xo[4] = {0, 0, 0, 0};
    #pragma unroll
    for (int j = 0; j < 8; j++) {
        float xj = xx[j];
        #pragma unroll
        for (int k = 0; k < 4; k++) {
            xe[k] = fmaf(xj, se[j * 4 + k], xe[k]);
            xo[k] = fmaf(xj, so[j * 4 + k], xo[k]);
        }
    }
    long ob = ((long)b * 2 * m + 2 * t) * 128 + c * 4;
    *(float4*)(xout + ob) = make_float4(xe[0], xe[1], xe[2], xe[3]);
    *(float4*)(xout + ob + 128) = make_float4(xo[0], xo[1], xo[2], xo[3]);
}

extern "C" void kernel_launch(void* const* d_in, const int* in_sizes, int n_in,
                              void* d_out, int out_size) {
    const float* x = (const float*)d_in[0];
    const float* W6[6];
    for (int i = 0; i < 6; i++) W6[i] = (const float*)d_in[1 + i];
    const float* small32[4] = {0, 0, 0, 0};
    const float* T0w = 0; const float* T0b = 0;
    int n32 = 0;
    for (int i = 7; i < n_in; i++) {
        int s = in_sizes[i];
        if (s == 32 && n32 < 4) small32[n32++] = (const float*)d_in[i];
        else if (s == 16) T0w = (const float*)d_in[i];
        else if (s == 4) T0b = (const float*)d_in[i];
    }
    const float* ec_s = small32[0];
    const float* ec_d = small32[1];
    const float* rc_e = small32[2];
    const float* rc_o = small32[3];

    float *pD, *pS, *pUD, *pUS, *pVFP, *pOF, *pWt;
    cudaGetSymbolAddress((void**)&pD, g_D);
    cudaGetSymbolAddress((void**)&pS, g_S);
    cudaGetSymbolAddress((void**)&pUD, g_UD);
    cudaGetSymbolAddress((void**)&pUS, g_US);
    cudaGetSymbolAddress((void**)&pVFP, g_VFP);
    cudaGetSymbolAddress((void**)&pOF, g_OF);
    cudaGetSymbolAddress((void**)&pWt, g_Wt);
    float* pS0 = pS;
    float* pS1 = pS + SBUF;

    k_init_tab_all<<<1024, 256>>>();
    {
        dim3 g(512, 4, 6);
        k_wt6<<<g, dim3(32, 8)>>>(W6[0], W6[1], W6[2], W6[3], W6[4], W6[5]);
    }

    const float* xin = x;
    for (int i = 0; i < NLEV; i++) {
        int m = h_m[i], l = h_l[i], toff = h_toff[i];
        int nsp = (m >= KCHUNK) ? (m / KCHUNK) : 1;
        float* sout = (i & 1) ? pS1 : pS0;
        int tot = BB * m * 32;
        k_dec<<<(tot + 255) / 256, 256>>>(xin, ec_s, ec_d, pD, sout, m);
        dim3 gf(1, 2, 32 * nsp);
        k_fwd<<<gf, 256>>>(pD, sout, pVFP, m, l, toff);
        dim3 gm(l, 2);
        k_mix2<<<gm, 128>>>(pWt, pVFP, nsp,
                            pOF + 0 * VFSZ, pOF + 1 * VFSZ,
                            pOF + 2 * VFSZ, pOF + 3 * VFSZ);
        dim3 gi((m + 127) / 128, 2, 16);
        k_inv<<<gi, 256>>>(pUD + (long)h_uoff[i] * (BB * CH),
                           pUS + (long)h_uoff[i] * (BB * CH),
                           pOF, m, l, toff);
        xin = sout;
    }

    k_t0<<<2, 256>>>(pS0, T0w, T0b, pS1);

    float* rin = pS1;
    for (int i = NLEV - 1; i >= 0; i--) {
        int m = h_m[i];
        float* rout = (i == 0) ? (float*)d_out : ((rin == pS1) ? pS0 : pS1);
        int tot = BB * m * 32;
        k_rec<<<(tot + 255) / 256, 256>>>(rin,
                                          pUD + (long)h_uoff[i] * (BB * CH),
                                          pUS + (long)h_uoff[i] * (BB * CH),
                                          rc_e, rc_o, rout, m);
        rin = rout;
    }
}